// round 1
// baseline (speedup 1.0000x reference)
#include <cuda_runtime.h>
#include <math.h>

#define H       16
#define DM      1024
#define DK      64
#define POS_DK  16
#define EMB_DIM 256
#define MAXD    1000
#define RES     20
#define N_EMB   (2*MAXD*RES + 1)   // 40001
#define BATCH   2
#define NQ      512
#define NK      512
#define MROWS   (BATCH*NQ)         // 1024

// ---------------- device scratch (no allocs allowed) ----------------
__device__ float g_px[N_EMB * H];            // 2.56 MB
__device__ float g_py[N_EMB * H];            // 2.56 MB
__device__ float g_Q [BATCH * H * NQ * DK];  // 4 MB   layout [b][h][q][d]
__device__ float g_Kt[BATCH * H * DK * NK];  // 4 MB   layout [b][h][d][n]  (transposed)
__device__ float g_V [BATCH * H * NK * DK];  // 4 MB   layout [b][h][n][d]
__device__ float g_attn[BATCH * NQ * DM];    // 4 MB   layout [b][q][h*64+d]

// ---------------- kernel 1: project pos tables with Wb --------------
// px[idx][h] = sum_{d<16} x_table[idx][h*16+d] * Wb[d]
__global__ void tables_kernel(const float* __restrict__ xt,
                              const float* __restrict__ yt,
                              const float* __restrict__ Wb) {
    int i = blockIdx.x * blockDim.x + threadIdx.x;
    if (i >= N_EMB * H) return;
    int idx = i >> 4;
    int h   = i & 15;
    const float* xr = xt + (size_t)idx * EMB_DIM + h * POS_DK;
    const float* yr = yt + (size_t)idx * EMB_DIM + h * POS_DK;
    float sx = 0.f, sy = 0.f;
#pragma unroll
    for (int d = 0; d < POS_DK; d++) {
        float w = __ldg(Wb + d);
        sx += xr[d] * w;
        sy += yr[d] * w;
    }
    g_px[i] = sx;
    g_py[i] = sy;
}

// ---------------- kernel 2: SGEMM  C = A(1024x1024) @ W(1024x1024) + b
// MODE 0: C[m][n]                         (plain, for final output)
// MODE 1: C[b][h][q][d]                   (Q / V head layout)
// MODE 2: C[b][h][d][q]                   (K transposed head layout)
template<int MODE>
__global__ __launch_bounds__(256, 2)
void sgemm_kernel(const float* __restrict__ A, const float* __restrict__ W,
                  const float* __restrict__ bias, float* __restrict__ C) {
    __shared__ float As[16][128];
    __shared__ float Bs[16][128];
    const int tid = threadIdx.x;
    const int m0 = blockIdx.y * 128;
    const int n0 = blockIdx.x * 128;
    const int tx = tid & 15;        // 0..15 -> 8 cols each
    const int ty = tid >> 4;        // 0..15 -> 8 rows each

    float acc[8][8];
#pragma unroll
    for (int i = 0; i < 8; i++)
#pragma unroll
        for (int j = 0; j < 8; j++) acc[i][j] = 0.f;

    for (int k0 = 0; k0 < 1024; k0 += 16) {
        // load A tile 128x16 (transpose into As[k][m])
#pragma unroll
        for (int i = 0; i < 2; i++) {
            int lin = tid + i * 256;          // 0..511 float4 slots
            int row = lin >> 2;               // 128 rows, 4 float4 per row
            int c4  = lin & 3;
            float4 v = *(const float4*)(A + (size_t)(m0 + row) * 1024 + k0 + c4 * 4);
            As[c4 * 4 + 0][row] = v.x;
            As[c4 * 4 + 1][row] = v.y;
            As[c4 * 4 + 2][row] = v.z;
            As[c4 * 4 + 3][row] = v.w;
        }
        // load W tile 16x128
#pragma unroll
        for (int i = 0; i < 2; i++) {
            int lin = tid + i * 256;
            int row = lin >> 5;               // 16 rows, 32 float4 per row
            int c4  = lin & 31;
            *(float4*)(&Bs[row][c4 * 4]) =
                *(const float4*)(W + (size_t)(k0 + row) * 1024 + n0 + c4 * 4);
        }
        __syncthreads();
#pragma unroll
        for (int k = 0; k < 16; k++) {
            float a[8], bf[8];
#pragma unroll
            for (int i = 0; i < 8; i++) a[i]  = As[k][ty * 8 + i];
#pragma unroll
            for (int j = 0; j < 8; j++) bf[j] = Bs[k][tx * 8 + j];
#pragma unroll
            for (int i = 0; i < 8; i++)
#pragma unroll
                for (int j = 0; j < 8; j++)
                    acc[i][j] += a[i] * bf[j];
        }
        __syncthreads();
    }

    // epilogue: add bias, scatter to requested layout
#pragma unroll
    for (int i = 0; i < 8; i++) {
        int m  = m0 + ty * 8 + i;
        int b  = m >> 9;       // /512
        int q  = m & 511;
#pragma unroll
        for (int j = 0; j < 8; j++) {
            int n = n0 + tx * 8 + j;
            float v = acc[i][j] + __ldg(bias + n);
            if (MODE == 0) {
                C[(size_t)m * 1024 + n] = v;
            } else {
                int h = n >> 6, d = n & 63;
                if (MODE == 1)
                    C[(((size_t)(b * H + h) * NQ + q) * DK) + d] = v;
                else
                    C[(((size_t)(b * H + h) * DK + d) * NK) + q] = v;
            }
        }
    }
}

// ---------------- kernel 3: fused scores + pos-bias + softmax + PV ----
// one block (128 threads) per (b, h, query-row qi)
__global__ __launch_bounds__(128)
void attn_kernel(const float* __restrict__ qx, const float* __restrict__ qy,
                 const float* __restrict__ kx, const float* __restrict__ ky,
                 const float* __restrict__ bbp) {
    const int qi = blockIdx.x;
    const int h  = blockIdx.y;
    const int b  = blockIdx.z;
    const int tid = threadIdx.x;     // 128

    __shared__ float qsh[DK];
    __shared__ float ssh[NK];
    __shared__ float red[4];
    __shared__ float osum[DK];

    const float* Qrow = g_Q  + ((size_t)(b * H + h) * NQ + qi) * DK;
    const float* Ktb  = g_Kt + (size_t)(b * H + h) * DK * NK;
    const float* Vb   = g_V  + (size_t)(b * H + h) * NK * DK;

    if (tid < DK) qsh[tid] = Qrow[tid];
    __syncthreads();

    // reference quirk: for score (query i, key j), diff = query_x[b,j] - key_x[b,i]
    const float kxi = kx[b * NK + qi];
    const float kyi = ky[b * NK + qi];
    const float bbv = __ldg(bbp);

    float sloc[4];
    float m = -1e30f;
#pragma unroll
    for (int jj = 0; jj < 4; jj++) {
        int j = tid + jj * 128;
        float s = 0.f;
#pragma unroll
        for (int d = 0; d < DK; d++)
            s += qsh[d] * Ktb[d * NK + j];
        float dx = qx[b * NQ + j] - kxi;
        float dy = qy[b * NQ + j] - kyi;
        dx = fminf(fmaxf(dx, -1000.f), 1000.f);
        dy = fminf(fmaxf(dy, -1000.f), 1000.f);
        int ix = (int)rintf((dx + 1000.f) * 20.f);
        int iy = (int)rintf((dy + 1000.f) * 20.f);
        float z = g_px[ix * H + h] + g_py[iy * H + h] + bbv;
        float biasv = 1.f / (1.f + expf(-z));
        s = s * 0.125f + biasv;          // 1/sqrt(64)
        sloc[jj] = s;
        m = fmaxf(m, s);
    }

    // block max
#pragma unroll
    for (int o = 16; o > 0; o >>= 1)
        m = fmaxf(m, __shfl_xor_sync(0xffffffffu, m, o));
    if ((tid & 31) == 0) red[tid >> 5] = m;
    __syncthreads();
    m = fmaxf(fmaxf(red[0], red[1]), fmaxf(red[2], red[3]));
    __syncthreads();   // protect red[] before reuse

    float lsum = 0.f;
#pragma unroll
    for (int jj = 0; jj < 4; jj++) {
        float e = expf(sloc[jj] - m);
        ssh[tid + jj * 128] = e;
        lsum += e;
    }
#pragma unroll
    for (int o = 16; o > 0; o >>= 1)
        lsum += __shfl_xor_sync(0xffffffffu, lsum, o);
    if ((tid & 31) == 0) red[tid >> 5] = lsum;
    __syncthreads();   // makes ssh + red visible
    const float inv = 1.f / (red[0] + red[1] + red[2] + red[3]);

    // P @ V : 2 half-blocks of 64 threads, each covers 256 keys
    const int d    = tid & 63;
    const int half = tid >> 6;
    float acc = 0.f;
    const int j0 = half * 256;
#pragma unroll 4
    for (int j = j0; j < j0 + 256; j++)
        acc += ssh[j] * Vb[(size_t)j * DK + d];
    if (half == 1) osum[d] = acc;
    __syncthreads();
    if (half == 0) {
        float tot = (acc + osum[d]) * inv;
        g_attn[((size_t)b * NQ + qi) * DM + h * DK + d] = tot;
    }
}

// ---------------- launcher -------------------------------------------
extern "C" void kernel_launch(void* const* d_in, const int* in_sizes, int n_in,
                              void* d_out, int out_size) {
    const float* query  = (const float*)d_in[0];
    const float* key    = (const float*)d_in[1];
    const float* value  = (const float*)d_in[2];
    const float* qx     = (const float*)d_in[3];
    const float* qy     = (const float*)d_in[4];
    const float* kx     = (const float*)d_in[5];
    const float* ky     = (const float*)d_in[6];
    const float* Wq     = (const float*)d_in[7];
    const float* bq     = (const float*)d_in[8];
    const float* Wk     = (const float*)d_in[9];
    const float* bk     = (const float*)d_in[10];
    const float* Wv     = (const float*)d_in[11];
    const float* bv     = (const float*)d_in[12];
    const float* Wo     = (const float*)d_in[13];
    const float* bo     = (const float*)d_in[14];
    const float* xtab   = (const float*)d_in[15];
    const float* ytab   = (const float*)d_in[16];
    const float* Wb     = (const float*)d_in[17];
    const float* bb     = (const float*)d_in[18];

    float *pQ, *pKt, *pV, *pAttn;
    cudaGetSymbolAddress((void**)&pQ,    g_Q);
    cudaGetSymbolAddress((void**)&pKt,   g_Kt);
    cudaGetSymbolAddress((void**)&pV,    g_V);
    cudaGetSymbolAddress((void**)&pAttn, g_attn);

    // 1. project pos tables
    tables_kernel<<<(N_EMB * H + 255) / 256, 256>>>(xtab, ytab, Wb);

    // 2. QKV projections (1024x1024x1024 each)
    dim3 gg(1024 / 128, MROWS / 128);   // (8, 8)
    sgemm_kernel<1><<<gg, 256>>>(query, Wq, bq, pQ);
    sgemm_kernel<2><<<gg, 256>>>(key,   Wk, bk, pKt);
    sgemm_kernel<1><<<gg, 256>>>(value, Wv, bv, pV);

    // 3. fused attention with position bias
    attn_kernel<<<dim3(NQ, H, BATCH), 128>>>(qx, qy, kx, ky, bb);

    // 4. output projection straight into d_out
    sgemm_kernel<0><<<gg, 256>>>(pAttn, Wo, bo, (float*)d_out);
}

// round 6
// speedup vs baseline: 2.6225x; 2.6225x over previous
#include <cuda_runtime.h>
#include <math.h>

#define H       16
#define DM      1024
#define DK      64
#define POS_DK  16
#define EMB_DIM 256
#define N_EMB   40001
#define BATCH   2
#define NQ      512
#define NK      512
#define MROWS   1024

// ---------------- device scratch (no allocs allowed) ----------------
__device__ float g_px[N_EMB * H];                  // 2.56 MB
__device__ float g_py[N_EMB * H];                  // 2.56 MB
__device__ float g_Q [BATCH * H * NQ * DK];        // [b][h][q][d]
__device__ float g_K [BATCH * H * NK * DK];        // [b][h][n][d]
__device__ float g_V [BATCH * H * NK * DK];        // [b][h][n][d]
__device__ float g_attn[BATCH * NQ * DM];          // [b][q][h*64+d]
__device__ float g_bias[(size_t)BATCH * H * NQ * NK]; // 33.5 MB  [b][h][q][k]

// ---------------- kernel 1: project pos tables with Wb --------------
__global__ void tables_kernel(const float* __restrict__ xt,
                              const float* __restrict__ yt,
                              const float* __restrict__ Wb) {
    int i = blockIdx.x * blockDim.x + threadIdx.x;
    if (i >= N_EMB * H) return;
    int idx = i >> 4;
    int h   = i & 15;
    const float* xr = xt + (size_t)idx * EMB_DIM + h * POS_DK;
    const float* yr = yt + (size_t)idx * EMB_DIM + h * POS_DK;
    float sx = 0.f, sy = 0.f;
#pragma unroll
    for (int d = 0; d < POS_DK; d++) {
        float w = __ldg(Wb + d);
        sx += xr[d] * w;
        sy += yr[d] * w;
    }
    g_px[i] = sx;
    g_py[i] = sy;
}

// ---------------- kernel 2: position bias, all 16 heads per (b,q,j) --
__global__ __launch_bounds__(256)
void bias_kernel(const float* __restrict__ qx, const float* __restrict__ qy,
                 const float* __restrict__ kx, const float* __restrict__ ky,
                 const float* __restrict__ bbp) {
    const int j = blockIdx.x * 256 + threadIdx.x;
    const int q = blockIdx.y;
    const int b = blockIdx.z;
    const float kxv = kx[b * NK + q];
    const float kyv = ky[b * NK + q];
    float dx = qx[b * NQ + j] - kxv;
    float dy = qy[b * NQ + j] - kyv;
    dx = fminf(fmaxf(dx, -1000.f), 1000.f);
    dy = fminf(fmaxf(dy, -1000.f), 1000.f);
    const int ix = (int)rintf((dx + 1000.f) * 20.f);
    const int iy = (int)rintf((dy + 1000.f) * 20.f);
    const float4* px4 = (const float4*)(g_px + ix * H);
    const float4* py4 = (const float4*)(g_py + iy * H);
    const float bb = __ldg(bbp);
    size_t base = ((size_t)(b * H) * NQ + q) * NK + j;   // h stride = NQ*NK
#pragma unroll
    for (int hh = 0; hh < 4; hh++) {
        float4 a = px4[hh];
        float4 c = py4[hh];
        float z0 = a.x + c.x + bb, z1 = a.y + c.y + bb;
        float z2 = a.z + c.z + bb, z3 = a.w + c.w + bb;
        g_bias[base + (size_t)(hh*4+0) * NQ * NK] = 1.f / (1.f + __expf(-z0));
        g_bias[base + (size_t)(hh*4+1) * NQ * NK] = 1.f / (1.f + __expf(-z1));
        g_bias[base + (size_t)(hh*4+2) * NQ * NK] = 1.f / (1.f + __expf(-z2));
        g_bias[base + (size_t)(hh*4+3) * NQ * NK] = 1.f / (1.f + __expf(-z3));
    }
}

// ---------------- 128x64-tile SGEMM body, double-buffered ------------
// mode 0: C[m][n]    mode 1: C[b][h][q][d]
__device__ __forceinline__ void gemm_tile(const float* __restrict__ A,
                                          const float* __restrict__ W,
                                          const float* __restrict__ bias,
                                          float* __restrict__ C, int mode) {
    __shared__ float As[2][16][128];   // 16 KB
    __shared__ float Bs[2][16][64];    //  8 KB
    const int tid = threadIdx.x;
    const int m0 = blockIdx.y * 128;
    const int n0 = blockIdx.x * 64;
    const int tx = tid & 15;        // 4 n-cols each
    const int ty = tid >> 4;        // 8 m-rows each

    // fixed per-thread load coordinates
    const int ar0 = tid >> 2;            // A rows (i=0): 0..63
    const int ar1 = (tid + 256) >> 2;    // A rows (i=1): 64..127
    const int ac4 = tid & 3;             // A float4 col within 16-k slice
    const int br  = tid >> 4;            // B row 0..15
    const int bc4 = tid & 15;            // B float4 col

    float acc[8][4];
#pragma unroll
    for (int i = 0; i < 8; i++)
#pragma unroll
        for (int j = 0; j < 4; j++) acc[i][j] = 0.f;

    float4 pa0, pa1, pb;
    // preload slice 0 into registers, store into buffer 0
    pa0 = *(const float4*)(A + (size_t)(m0 + ar0) * 1024 + ac4 * 4);
    pa1 = *(const float4*)(A + (size_t)(m0 + ar1) * 1024 + ac4 * 4);
    pb  = *(const float4*)(W + (size_t)br * 1024 + n0 + bc4 * 4);
    As[0][ac4 * 4 + 0][ar0] = pa0.x; As[0][ac4 * 4 + 1][ar0] = pa0.y;
    As[0][ac4 * 4 + 2][ar0] = pa0.z; As[0][ac4 * 4 + 3][ar0] = pa0.w;
    As[0][ac4 * 4 + 0][ar1] = pa1.x; As[0][ac4 * 4 + 1][ar1] = pa1.y;
    As[0][ac4 * 4 + 2][ar1] = pa1.z; As[0][ac4 * 4 + 3][ar1] = pa1.w;
    *(float4*)&Bs[0][br][bc4 * 4] = pb;
    __syncthreads();

    for (int k0 = 0; k0 < 1024; k0 += 16) {
        const int cur = (k0 >> 4) & 1;
        const bool hasNext = (k0 + 16) < 1024;
        // prefetch next slice into registers (overlaps with compute below)
        if (hasNext) {
            pa0 = *(const float4*)(A + (size_t)(m0 + ar0) * 1024 + (k0 + 16) + ac4 * 4);
            pa1 = *(const float4*)(A + (size_t)(m0 + ar1) * 1024 + (k0 + 16) + ac4 * 4);
            pb  = *(const float4*)(W + (size_t)(k0 + 16 + br) * 1024 + n0 + bc4 * 4);
        }
        // compute current slice
#pragma unroll
        for (int k = 0; k < 16; k++) {
            float4 a0 = *(const float4*)&As[cur][k][ty * 8];
            float4 a1 = *(const float4*)&As[cur][k][ty * 8 + 4];
            float4 bv = *(const float4*)&Bs[cur][k][tx * 4];
            float av[8] = {a0.x, a0.y, a0.z, a0.w, a1.x, a1.y, a1.z, a1.w};
            float bf[4] = {bv.x, bv.y, bv.z, bv.w};
#pragma unroll
            for (int i = 0; i < 8; i++)
#pragma unroll
                for (int j = 0; j < 4; j++)
                    acc[i][j] += av[i] * bf[j];
        }
        // commit prefetched slice to the alternate buffer
        if (hasNext) {
            const int nxt = cur ^ 1;
            As[nxt][ac4 * 4 + 0][ar0] = pa0.x; As[nxt][ac4 * 4 + 1][ar0] = pa0.y;
            As[nxt][ac4 * 4 + 2][ar0] = pa0.z; As[nxt][ac4 * 4 + 3][ar0] = pa0.w;
            As[nxt][ac4 * 4 + 0][ar1] = pa1.x; As[nxt][ac4 * 4 + 1][ar1] = pa1.y;
            As[nxt][ac4 * 4 + 2][ar1] = pa1.z; As[nxt][ac4 * 4 + 3][ar1] = pa1.w;
            *(float4*)&Bs[nxt][br][bc4 * 4] = pb;
        }
        __syncthreads();
    }

    const int n = n0 + tx * 4;
    float4 bv = *(const float4*)(bias + n);
    if (mode == 0) {
#pragma unroll
        for (int i = 0; i < 8; i++) {
            int m = m0 + ty * 8 + i;
            float4 o = {acc[i][0] + bv.x, acc[i][1] + bv.y,
                        acc[i][2] + bv.z, acc[i][3] + bv.w};
            *(float4*)(C + (size_t)m * 1024 + n) = o;
        }
    } else {
        const int hh = n >> 6, d = n & 63;
#pragma unroll
        for (int i = 0; i < 8; i++) {
            int m = m0 + ty * 8 + i;
            int b = m >> 9, q = m & 511;
            float4 o = {acc[i][0] + bv.x, acc[i][1] + bv.y,
                        acc[i][2] + bv.z, acc[i][3] + bv.w};
            *(float4*)(C + (((size_t)(b * H + hh) * NQ + q) * DK) + d) = o;
        }
    }
}

// fused QKV: grid.z selects which projection
__global__ __launch_bounds__(256, 3)
void gemm_qkv(const float* __restrict__ Aq, const float* __restrict__ Ak,
              const float* __restrict__ Av,
              const float* __restrict__ Wq, const float* __restrict__ Wk,
              const float* __restrict__ Wv,
              const float* __restrict__ bq, const float* __restrict__ bk,
              const float* __restrict__ bv,
              float* Cq, float* Ck, float* Cv) {
    const int z = blockIdx.z;
    const float* A = (z == 0) ? Aq : (z == 1) ? Ak : Av;
    const float* W = (z == 0) ? Wq : (z == 1) ? Wk : Wv;
    const float* bb = (z == 0) ? bq : (z == 1) ? bk : bv;
    float* C = (z == 0) ? Cq : (z == 1) ? Ck : Cv;
    gemm_tile(A, W, bb, C, 1);
}

__global__ __launch_bounds__(256, 3)
void gemm_plain(const float* __restrict__ A, const float* __restrict__ W,
                const float* __restrict__ bias, float* __restrict__ C) {
    gemm_tile(A, W, bias, C, 0);
}

// ---------------- kernel 3: tiled attention (32 q-rows / block) ------
// smem: Qs[32][68] | KVs[64][68] | Sc[32][512] | rsum[32]
#define QS_OFF   0
#define KV_OFF   (32 * 68)
#define SC_OFF   (KV_OFF + 64 * 68)
#define RS_OFF   (SC_OFF + 32 * 512)
#define SMEM_FLOATS (RS_OFF + 32)

__global__ __launch_bounds__(256, 2)
void attn_kernel() {
    extern __shared__ float sm[];
    float* Qs  = sm + QS_OFF;
    float* KVs = sm + KV_OFF;
    float* Sc  = sm + SC_OFF;
    float* rsum = sm + RS_OFF;

    const int tid = threadIdx.x;
    const int q0  = blockIdx.x * 32;
    const int h   = blockIdx.y;
    const int b   = blockIdx.z;

    const float* Qg = g_Q + ((size_t)(b * H + h) * NQ + q0) * DK;
    const float* Kg = g_K + (size_t)(b * H + h) * NK * DK;
    const float* Vg = g_V + (size_t)(b * H + h) * NK * DK;
    const float* Bg = g_bias + ((size_t)(b * H + h) * NQ + q0) * NK;

    // stage Q (32x64)
#pragma unroll
    for (int i = 0; i < 2; i++) {
        int lin = tid + i * 256;
        int row = lin >> 4, c4 = lin & 15;
        *(float4*)&Qs[row * 68 + c4 * 4] =
            *(const float4*)(Qg + (size_t)row * 64 + c4 * 4);
    }

    const int tx = tid & 31;      // j lanes
    const int ty = tid >> 5;      // 0..7  (q = ty + 8*qq)

    // ---- score phase: S = QK^T/8 + bias ----
    for (int j0 = 0; j0 < NK; j0 += 64) {
        __syncthreads();
#pragma unroll
        for (int i = 0; i < 4; i++) {
            int lin = tid + i * 256;
            int row = lin >> 4, c4 = lin & 15;
            *(float4*)&KVs[row * 68 + c4 * 4] =
                *(const float4*)(Kg + (size_t)(j0 + row) * 64 + c4 * 4);
        }
        __syncthreads();
        float s[4][2];
#pragma unroll
        for (int qq = 0; qq < 4; qq++) { s[qq][0] = 0.f; s[qq][1] = 0.f; }
#pragma unroll
        for (int d = 0; d < 64; d += 4) {
            float4 k0v = *(const float4*)&KVs[tx * 68 + d];
            float4 k1v = *(const float4*)&KVs[(tx + 32) * 68 + d];
#pragma unroll
            for (int qq = 0; qq < 4; qq++) {
                float4 qv = *(const float4*)&Qs[(ty + 8 * qq) * 68 + d];
                s[qq][0] += qv.x * k0v.x + qv.y * k0v.y + qv.z * k0v.z + qv.w * k0v.w;
                s[qq][1] += qv.x * k1v.x + qv.y * k1v.y + qv.z * k1v.z + qv.w * k1v.w;
            }
        }
#pragma unroll
        for (int qq = 0; qq < 4; qq++) {
            int q = ty + 8 * qq;
#pragma unroll
            for (int jj = 0; jj < 2; jj++) {
                int j = tx + 32 * jj;
                Sc[q * 512 + j0 + j] =
                    s[qq][jj] * 0.125f + Bg[(size_t)q * NK + j0 + j];
            }
        }
    }
    __syncthreads();

    // ---- softmax per row (8 warps x 4 rows) ----
    {
        const int w = tid >> 5, lane = tid & 31;
#pragma unroll
        for (int r8 = 0; r8 < 4; r8++) {
            int row = w * 4 + r8;
            float m = -1e30f;
            for (int j = lane; j < 512; j += 32)
                m = fmaxf(m, Sc[row * 512 + j]);
#pragma unroll
            for (int o = 16; o > 0; o >>= 1)
                m = fmaxf(m, __shfl_xor_sync(0xffffffffu, m, o));
            float sum = 0.f;
            for (int j = lane; j < 512; j += 32) {
                float e = __expf(Sc[row * 512 + j] - m);
                Sc[row * 512 + j] = e;
                sum += e;
            }
#pragma unroll
            for (int o = 16; o > 0; o >>= 1)
                sum += __shfl_xor_sync(0xffffffffu, sum, o);
            if (lane == 0) rsum[row] = sum;
        }
    }

    // ---- PV phase ----
    const int d0 = (tid & 15) * 4;
    const int qp = tid >> 4;           // 0..15 -> q = 2*qp + {0,1}
    float4 acc0 = {0.f, 0.f, 0.f, 0.f};
    float4 acc1 = {0.f, 0.f, 0.f, 0.f};
    for (int j0 = 0; j0 < NK; j0 += 64) {
        __syncthreads();
#pragma unroll
        for (int i = 0; i < 4; i++) {
            int lin = tid + i * 256;
            int row = lin >> 4, c4 = lin & 15;
            *(float4*)&KVs[row * 68 + c4 * 4] =
                *(const float4*)(Vg + (size_t)(j0 + row) * 64 + c4 * 4);
        }
        __syncthreads();
#pragma unroll 8
        for (int j = 0; j < 64; j++) {
            float4 vv = *(const float4*)&KVs[j * 68 + d0];
            float p0 = Sc[(2 * qp)     * 512 + j0 + j];
            float p1 = Sc[(2 * qp + 1) * 512 + j0 + j];
            acc0.x += p0 * vv.x; acc0.y += p0 * vv.y;
            acc0.z += p0 * vv.z; acc0.w += p0 * vv.w;
            acc1.x += p1 * vv.x; acc1.y += p1 * vv.y;
            acc1.z += p1 * vv.z; acc1.w += p1 * vv.w;
        }
    }
    const float inv0 = 1.f / rsum[2 * qp];
    const float inv1 = 1.f / rsum[2 * qp + 1];
    float* o0 = g_attn + ((size_t)b * NQ + q0 + 2 * qp) * DM + h * DK + d0;
    float4 r0 = {acc0.x * inv0, acc0.y * inv0, acc0.z * inv0, acc0.w * inv0};
    float4 r1 = {acc1.x * inv1, acc1.y * inv1, acc1.z * inv1, acc1.w * inv1};
    *(float4*)o0 = r0;
    *(float4*)(o0 + DM) = r1;
}

// ---------------- launcher -------------------------------------------
extern "C" void kernel_launch(void* const* d_in, const int* in_sizes, int n_in,
                              void* d_out, int out_size) {
    const float* query  = (const float*)d_in[0];
    const float* key    = (const float*)d_in[1];
    const float* value  = (const float*)d_in[2];
    const float* qx     = (const float*)d_in[3];
    const float* qy     = (const float*)d_in[4];
    const float* kx     = (const float*)d_in[5];
    const float* ky     = (const float*)d_in[6];
    const float* Wq     = (const float*)d_in[7];
    const float* bq     = (const float*)d_in[8];
    const float* Wk     = (const float*)d_in[9];
    const float* bk     = (const float*)d_in[10];
    const float* Wv     = (const float*)d_in[11];
    const float* bv     = (const float*)d_in[12];
    const float* Wo     = (const float*)d_in[13];
    const float* bo     = (const float*)d_in[14];
    const float* xtab   = (const float*)d_in[15];
    const float* ytab   = (const float*)d_in[16];
    const float* Wb     = (const float*)d_in[17];
    const float* bb     = (const float*)d_in[18];

    float *pQ, *pK, *pV, *pAttn;
    cudaGetSymbolAddress((void**)&pQ,    g_Q);
    cudaGetSymbolAddress((void**)&pK,    g_K);
    cudaGetSymbolAddress((void**)&pV,    g_V);
    cudaGetSymbolAddress((void**)&pAttn, g_attn);

    cudaFuncSetAttribute(attn_kernel,
                         cudaFuncAttributeMaxDynamicSharedMemorySize,
                         SMEM_FLOATS * sizeof(float));

    // 1. project pos tables
    tables_kernel<<<(N_EMB * H + 255) / 256, 256>>>(xtab, ytab, Wb);

    // 2. position bias (all heads per pair)
    bias_kernel<<<dim3(NK / 256, NQ, BATCH), 256>>>(qx, qy, kx, ky, bb);

    // 3. fused QKV projections: 384 blocks fill the chip
    gemm_qkv<<<dim3(1024 / 64, MROWS / 128, 3), 256>>>(
        query, key, value, Wq, Wk, Wv, bq, bk, bv, pQ, pK, pV);

    // 4. tiled attention
    attn_kernel<<<dim3(NQ / 32, H, BATCH), 256, SMEM_FLOATS * sizeof(float)>>>();

    // 5. output projection into d_out
    gemm_plain<<<dim3(1024 / 64, MROWS / 128), 256>>>(pAttn, Wo, bo, (float*)d_out);
}